// round 6
// baseline (speedup 1.0000x reference)
#include <cuda_runtime.h>
#include <cuda_bf16.h>
#include <math.h>

#define U_NODES 200000
#define I_NODES 100000
#define N_NODES 300000
#define E_EDGES 1000000
#define DD 64
#define NB_SCAN 293   // ceil(300000/1024)

// ---------------- scratch (static device globals; no allocation) ----------------
__device__ float g_w[E_EDGES];
__device__ float g_deg[N_NODES];
__device__ float g_dis[N_NODES];
__device__ int   g_cnt[N_NODES];
__device__ int   g_ptr[N_NODES + 1];
__device__ int   g_cur[N_NODES];
__device__ int   g_bsum[NB_SCAN];
__device__ int   g_boff[NB_SCAN];
__device__ __align__(16) uint2 g_edge[2 * E_EDGES];   // {neighbor idx, float bits of norm}
__device__ __align__(16) float g_xA[(size_t)N_NODES * DD];
__device__ __align__(16) float g_xB[(size_t)N_NODES * DD];
__device__ __align__(16) float g_acc[(size_t)N_NODES * DD];

// ---------------- init: deg = 1 (self loop), cnt = 0 ----------------
__global__ void init_kernel() {
    int i = blockIdx.x * blockDim.x + threadIdx.x;
    if (i < N_NODES) { g_deg[i] = 1.0f; g_cnt[i] = 0; }
}

// ---------------- edge MLP + degree/count accumulation ----------------
__global__ void edge_mlp_kernel(const float* __restrict__ attr,
                                const int* __restrict__ src,
                                const int* __restrict__ dst,
                                const float* __restrict__ W1,
                                const float* __restrict__ b1,
                                const float* __restrict__ W2,
                                const float* __restrict__ b2) {
    __shared__ float sW1[8 * 32];
    __shared__ float sb1[32];
    __shared__ float sW2[32];
    __shared__ float sb2;
    int t = threadIdx.x;
    if (t < 256) sW1[t] = W1[t];
    if (t < 32) { sb1[t] = b1[t]; sW2[t] = W2[t]; }
    if (t == 0) sb2 = b2[0];
    __syncthreads();

    int e = blockIdx.x * blockDim.x + t;
    if (e >= E_EDGES) return;

    const float4* ap = (const float4*)(attr + (size_t)e * 8);
    float4 a0 = ap[0], a1 = ap[1];
    float a[8] = {a0.x, a0.y, a0.z, a0.w, a1.x, a1.y, a1.z, a1.w};

    float z = sb2;
#pragma unroll
    for (int j = 0; j < 32; j++) {
        float h = sb1[j];
#pragma unroll
        for (int k = 0; k < 8; k++) h = fmaf(a[k], sW1[k * 32 + j], h);
        z = fmaf(fmaxf(h, 0.0f), sW2[j], z);
    }
    float w = 1.0f / (1.0f + __expf(-z));
    w = fmaxf(w, 1e-6f);
    g_w[e] = w;

    int s = src[e];
    int d = dst[e] + U_NODES;
    atomicAdd(&g_deg[s], w);
    atomicAdd(&g_deg[d], w);
    atomicAdd(&g_cnt[s], 1);
    atomicAdd(&g_cnt[d], 1);
}

// ---------------- phase 1: per-block sums + dis = rsqrt(deg) fused ----------------
__global__ void blocksum_kernel() {
    __shared__ int ws[32];
    int t = threadIdx.x;
    int i = blockIdx.x * 1024 + t;
    int v = 0;
    if (i < N_NODES) {
        v = g_cnt[i];
        g_dis[i] = rsqrtf(g_deg[i]);
    }
    int s0 = v;
#pragma unroll
    for (int o = 16; o; o >>= 1) s0 += __shfl_xor_sync(0xffffffffu, s0, o);
    if ((t & 31) == 0) ws[t >> 5] = s0;
    __syncthreads();
    if (t < 32) {
        int s = ws[t];
#pragma unroll
        for (int o = 16; o; o >>= 1) s += __shfl_xor_sync(0xffffffffu, s, o);
        if (t == 0) g_bsum[blockIdx.x] = s;
    }
}

// ---------------- phase 2: exclusive scan of 293 block sums (1 block) ----------------
__global__ void bscan_kernel() {
    __shared__ int ws[16];
    int t = threadIdx.x; // 512 threads
    int v = (t < NB_SCAN) ? g_bsum[t] : 0;
    int x = v;
#pragma unroll
    for (int o = 1; o < 32; o <<= 1) {
        int tmp = __shfl_up_sync(0xffffffffu, x, o);
        if ((t & 31) >= o) x += tmp;
    }
    if ((t & 31) == 31) ws[t >> 5] = x;
    __syncthreads();
    if (t < 16) {
        int s = ws[t];
#pragma unroll
        for (int o = 1; o < 16; o <<= 1) {
            int tmp = __shfl_up_sync(0x0000ffffu, s, o);
            if (t >= o) s += tmp;
        }
        ws[t] = s;
    }
    __syncthreads();
    int wp = (t >= 32) ? ws[(t >> 5) - 1] : 0;
    int incl = x + wp;
    if (t < NB_SCAN) g_boff[t] = incl - v;
    if (t == NB_SCAN - 1) g_ptr[N_NODES] = incl;
}

// ---------------- phase 3: per-block local scan + offset -> ptr, cur ----------------
__global__ void ptr_kernel() {
    __shared__ int ws[32];
    int t = threadIdx.x;
    int i = blockIdx.x * 1024 + t;
    int v = (i < N_NODES) ? g_cnt[i] : 0;
    int x = v;
#pragma unroll
    for (int o = 1; o < 32; o <<= 1) {
        int tmp = __shfl_up_sync(0xffffffffu, x, o);
        if ((t & 31) >= o) x += tmp;
    }
    if ((t & 31) == 31) ws[t >> 5] = x;
    __syncthreads();
    if (t < 32) {
        int s = ws[t];
#pragma unroll
        for (int o = 1; o < 32; o <<= 1) {
            int tmp = __shfl_up_sync(0xffffffffu, s, o);
            if (t >= o) s += tmp;
        }
        ws[t] = s;
    }
    __syncthreads();
    int wp = (t >= 32) ? ws[(t >> 5) - 1] : 0;
    int excl = (x - v) + wp + g_boff[blockIdx.x];
    if (i < N_NODES) { g_ptr[i] = excl; g_cur[i] = excl; }
}

// ---------------- scatter edges into interleaved CSR ----------------
__global__ void scatter_kernel(const int* __restrict__ src,
                               const int* __restrict__ dst) {
    int e = blockIdx.x * blockDim.x + threadIdx.x;
    if (e >= E_EDGES) return;
    int s = src[e];
    int d = dst[e] + U_NODES;
    float nf = g_dis[s] * g_w[e] * g_dis[d];
    unsigned wb = __float_as_uint(nf);
    int p1 = atomicAdd(&g_cur[d], 1);
    g_edge[p1] = make_uint2((unsigned)s, wb);
    int p2 = atomicAdd(&g_cur[s], 1);
    g_edge[p2] = make_uint2((unsigned)d, wb);
}

// ---------------- user init: l2norm(user_w) -> xA  (16 lanes/node, float4) ----------------
__global__ void user_init_kernel(const float* __restrict__ uw) {
    int gid = blockIdx.x * blockDim.x + threadIdx.x;
    int n = gid >> 4;
    if (n >= U_NODES) return;
    int lane = threadIdx.x & 15;
    float4 v = ((const float4*)uw)[(size_t)n * 16 + lane];
    float s = v.x * v.x + v.y * v.y + v.z * v.z + v.w * v.w;
#pragma unroll
    for (int o = 8; o; o >>= 1) s += __shfl_xor_sync(0xffffffffu, s, o);
    float inv = 1.0f / fmaxf(sqrtf(s), 1e-12f);
    float4 out = make_float4(v.x * inv, v.y * inv, v.z * inv, v.w * inv);
    ((float4*)g_xA)[(size_t)n * 16 + lane] = out;
}

// ---------------- item init: register-tiled GEMM (64 items/block, 4x4 tile, 256 thr) ----------------
__global__ void item_init_kernel(const float* __restrict__ audio,
                                 const float* __restrict__ artw,
                                 const float* __restrict__ albw,
                                 const int* __restrict__ aid,
                                 const int* __restrict__ alid,
                                 const float* __restrict__ Wp,
                                 const float* __restrict__ bp) {
    __shared__ __align__(16) float sIn[128 * 64];   // [k][item]  32 KB
    __shared__ float sRed[64 * 17];                 // per-item partial sums (padded)
    __shared__ float sInv[64];
    int t = threadIdx.x;
    int item0 = blockIdx.x * 64;
    int w = t >> 5, l = t & 31;
    int item_local = ((w & 1) << 5) + l;     // 0..63, lanes span items
    int item = item0 + item_local;
    bool valid = item < I_NODES;
    int cbase = w >> 1;                      // 0..3

    int a_id = valid ? aid[item] : 0;
    int al_id = valid ? alid[item] : 0;

#pragma unroll
    for (int j = 0; j < 8; j++) {
        int c = cbase + 4 * j;               // float4 chunk 0..31
        float4 v;
        if (!valid) v = make_float4(0.f, 0.f, 0.f, 0.f);
        else if (c < 16) v = ((const float4*)(audio + (size_t)item * 64))[c];
        else {
            float4 x1 = ((const float4*)(artw + (size_t)a_id * 64))[c - 16];
            float4 x2 = ((const float4*)(albw + (size_t)al_id * 64))[c - 16];
            v = make_float4(x1.x + x2.x, x1.y + x2.y, x1.z + x2.z, x1.w + x2.w);
        }
        int k = c * 4;
        sIn[(k + 0) * 64 + item_local] = v.x;
        sIn[(k + 1) * 64 + item_local] = v.y;
        sIn[(k + 2) * 64 + item_local] = v.z;
        sIn[(k + 3) * 64 + item_local] = v.w;
    }
    __syncthreads();

    int tx = t & 15;   // column group (cols tx*4..+3)
    int ty = t >> 4;   // item group   (items ty*4..+3)
    float4 bp4 = ((const float4*)bp)[tx];
    float acc[4][4];
#pragma unroll
    for (int i = 0; i < 4; i++) {
        acc[i][0] = bp4.x; acc[i][1] = bp4.y; acc[i][2] = bp4.z; acc[i][3] = bp4.w;
    }
    const float4* Wp4 = (const float4*)Wp;
#pragma unroll 4
    for (int k = 0; k < 128; k++) {
        float4 in4 = *(const float4*)(sIn + k * 64 + ty * 4);
        float4 w4 = __ldg(Wp4 + k * 16 + tx);   // L1-resident (32 KB)
        float vi[4] = {in4.x, in4.y, in4.z, in4.w};
#pragma unroll
        for (int i = 0; i < 4; i++) {
            acc[i][0] = fmaf(vi[i], w4.x, acc[i][0]);
            acc[i][1] = fmaf(vi[i], w4.y, acc[i][1]);
            acc[i][2] = fmaf(vi[i], w4.z, acc[i][2]);
            acc[i][3] = fmaf(vi[i], w4.w, acc[i][3]);
        }
    }
#pragma unroll
    for (int i = 0; i < 4; i++) {
        float p = acc[i][0] * acc[i][0] + acc[i][1] * acc[i][1]
                + acc[i][2] * acc[i][2] + acc[i][3] * acc[i][3];
        sRed[(ty * 4 + i) * 17 + tx] = p;
    }
    __syncthreads();
    if (t < 64) {
        float s = 0.f;
#pragma unroll
        for (int q = 0; q < 16; q++) s += sRed[t * 17 + q];
        sInv[t] = 1.0f / fmaxf(sqrtf(s), 1e-12f);
    }
    __syncthreads();
#pragma unroll
    for (int i = 0; i < 4; i++) {
        int il = ty * 4 + i;
        int it = item0 + il;
        if (it < I_NODES) {
            float inv = sInv[il];
            float4 o = make_float4(acc[i][0] * inv, acc[i][1] * inv,
                                   acc[i][2] * inv, acc[i][3] * inv);
            ((float4*)g_xA)[(size_t)(U_NODES + it) * 16 + tx] = o;
        }
    }
}

// ---------------- one LGConv layer (16 lanes/node, float4, unroll 4) ----------------
// MODE 0: layer1  xA->xB — write xout, write acc = self_raw + a (no acc read)
// MODE 1: layer2  xB->xA — write xout, acc += a
// MODE 2: layer3  xA->out — fused final: out = l2norm((acc + a)/4), no xout write
template<int MODE>
__global__ void gather_kernel(float* __restrict__ outp) {
    const float4* xin = (MODE == 1) ? (const float4*)g_xB : (const float4*)g_xA;
    float4* xout = (MODE == 0) ? (float4*)g_xB : (float4*)g_xA;

    int gid = blockIdx.x * blockDim.x + threadIdx.x;
    int n = gid >> 4;
    if (n >= N_NODES) return;
    int lane = threadIdx.x & 15;

    float4 self = __ldg(xin + (size_t)n * 16 + lane);
    float dv = g_dis[n];
    float sw = dv * dv;
    float4 a = make_float4(self.x * sw, self.y * sw, self.z * sw, self.w * sw);
    float4 a2 = make_float4(0.f, 0.f, 0.f, 0.f);

    int e = g_ptr[n];
    int end = g_ptr[n + 1];
    for (; e + 4 <= end; e += 4) {
        uint2 q0 = __ldg(g_edge + e + 0);
        uint2 q1 = __ldg(g_edge + e + 1);
        uint2 q2 = __ldg(g_edge + e + 2);
        uint2 q3 = __ldg(g_edge + e + 3);
        float v0 = __uint_as_float(q0.y);
        float v1 = __uint_as_float(q1.y);
        float v2 = __uint_as_float(q2.y);
        float v3 = __uint_as_float(q3.y);
        float4 x0 = __ldg(xin + (size_t)q0.x * 16 + lane);
        float4 x1 = __ldg(xin + (size_t)q1.x * 16 + lane);
        float4 x2 = __ldg(xin + (size_t)q2.x * 16 + lane);
        float4 x3 = __ldg(xin + (size_t)q3.x * 16 + lane);
        a.x  = fmaf(v0, x0.x, a.x);  a.y  = fmaf(v0, x0.y, a.y);
        a.z  = fmaf(v0, x0.z, a.z);  a.w  = fmaf(v0, x0.w, a.w);
        a.x  = fmaf(v1, x1.x, a.x);  a.y  = fmaf(v1, x1.y, a.y);
        a.z  = fmaf(v1, x1.z, a.z);  a.w  = fmaf(v1, x1.w, a.w);
        a2.x = fmaf(v2, x2.x, a2.x); a2.y = fmaf(v2, x2.y, a2.y);
        a2.z = fmaf(v2, x2.z, a2.z); a2.w = fmaf(v2, x2.w, a2.w);
        a2.x = fmaf(v3, x3.x, a2.x); a2.y = fmaf(v3, x3.y, a2.y);
        a2.z = fmaf(v3, x3.z, a2.z); a2.w = fmaf(v3, x3.w, a2.w);
    }
    for (; e < end; e++) {
        uint2 q = __ldg(g_edge + e);
        float v0 = __uint_as_float(q.y);
        float4 x0 = __ldg(xin + (size_t)q.x * 16 + lane);
        a.x = fmaf(v0, x0.x, a.x); a.y = fmaf(v0, x0.y, a.y);
        a.z = fmaf(v0, x0.z, a.z); a.w = fmaf(v0, x0.w, a.w);
    }
    a.x += a2.x; a.y += a2.y; a.z += a2.z; a.w += a2.w;

    if (MODE == 0) {
        xout[(size_t)n * 16 + lane] = a;
        float4 c = make_float4(self.x + a.x, self.y + a.y, self.z + a.z, self.w + a.w);
        ((float4*)g_acc)[(size_t)n * 16 + lane] = c;
    } else if (MODE == 1) {
        xout[(size_t)n * 16 + lane] = a;
        float4 c = ((const float4*)g_acc)[(size_t)n * 16 + lane];
        c.x += a.x; c.y += a.y; c.z += a.z; c.w += a.w;
        ((float4*)g_acc)[(size_t)n * 16 + lane] = c;
    } else {
        float4 c = ((const float4*)g_acc)[(size_t)n * 16 + lane];
        c.x = (c.x + a.x) * 0.25f;
        c.y = (c.y + a.y) * 0.25f;
        c.z = (c.z + a.z) * 0.25f;
        c.w = (c.w + a.w) * 0.25f;
        float s = c.x * c.x + c.y * c.y + c.z * c.z + c.w * c.w;
#pragma unroll
        for (int o = 8; o; o >>= 1) s += __shfl_xor_sync(0xffffffffu, s, o);
        float inv = 1.0f / fmaxf(sqrtf(s), 1e-12f);
        ((float4*)outp)[(size_t)n * 16 + lane] =
            make_float4(c.x * inv, c.y * inv, c.z * inv, c.w * inv);
    }
}

// ---------------- side stream + events, created once at static-init time ----------------
__global__ void warmup_kernel() {}

namespace {
struct SideStream {
    cudaStream_t s2 = 0;
    cudaEvent_t evFork = 0, evJoin = 0;
    bool ok = false;
    SideStream() {
        if (cudaStreamCreateWithFlags(&s2, cudaStreamNonBlocking) != cudaSuccess) return;
        if (cudaEventCreateWithFlags(&evFork, cudaEventDisableTiming) != cudaSuccess) return;
        if (cudaEventCreateWithFlags(&evJoin, cudaEventDisableTiming) != cudaSuccess) return;
        warmup_kernel<<<1, 32>>>();
        warmup_kernel<<<1, 32, 0, s2>>>();
        if (cudaDeviceSynchronize() != cudaSuccess) return;
        ok = true;
    }
};
SideStream g_side;
}

extern "C" void kernel_launch(void* const* d_in, const int* in_sizes, int n_in,
                              void* d_out, int out_size) {
    const int*   edge_src   = (const int*)d_in[0];
    const int*   edge_dst   = (const int*)d_in[1];
    const float* edge_attr  = (const float*)d_in[2];
    const float* user_w     = (const float*)d_in[3];
    const float* artist_w   = (const float*)d_in[4];
    const float* album_w    = (const float*)d_in[5];
    const float* item_audio = (const float*)d_in[6];
    const int*   artist_ids = (const int*)d_in[7];
    const int*   album_ids  = (const int*)d_in[8];
    const float* Wp         = (const float*)d_in[9];
    const float* bp         = (const float*)d_in[10];
    const float* W1         = (const float*)d_in[11];
    const float* b1         = (const float*)d_in[12];
    const float* W2         = (const float*)d_in[13];
    const float* b2         = (const float*)d_in[14];
    float* out = (float*)d_out;

    const int TPB = 256;
    bool fork = g_side.ok;
    cudaStream_t sB = fork ? g_side.s2 : (cudaStream_t)0;

    if (fork) {
        cudaEventRecord(g_side.evFork, 0);
        cudaStreamWaitEvent(sB, g_side.evFork, 0);
    }

    // ---- chain B (side stream): node feature init ----
    user_init_kernel<<<(U_NODES * 16 + TPB - 1) / TPB, TPB, 0, sB>>>(user_w);
    item_init_kernel<<<(I_NODES + 63) / 64, TPB, 0, sB>>>(item_audio, artist_w, album_w,
                                                          artist_ids, album_ids, Wp, bp);
    if (fork) cudaEventRecord(g_side.evJoin, sB);

    // ---- chain A (main stream): graph build ----
    init_kernel<<<(N_NODES + TPB - 1) / TPB, TPB>>>();
    edge_mlp_kernel<<<(E_EDGES + TPB - 1) / TPB, TPB>>>(edge_attr, edge_src, edge_dst,
                                                        W1, b1, W2, b2);
    blocksum_kernel<<<NB_SCAN, 1024>>>();   // also computes g_dis
    bscan_kernel<<<1, 512>>>();
    ptr_kernel<<<NB_SCAN, 1024>>>();
    scatter_kernel<<<(E_EDGES + TPB - 1) / TPB, TPB>>>(edge_src, edge_dst);

    if (fork) cudaStreamWaitEvent((cudaStream_t)0, g_side.evJoin, 0);

    // ---- 3 propagation layers ----
    int nblocks = (N_NODES * 16 + TPB - 1) / TPB;
    gather_kernel<0><<<nblocks, TPB>>>(nullptr);
    gather_kernel<1><<<nblocks, TPB>>>(nullptr);
    gather_kernel<2><<<nblocks, TPB>>>(out);
}

// round 7
// speedup vs baseline: 1.1779x; 1.1779x over previous
#include <cuda_runtime.h>
#include <cuda_fp16.h>
#include <math.h>

#define U_NODES 200000
#define I_NODES 100000
#define N_NODES 300000
#define E_EDGES 1000000
#define DD 64
#define NB_SCAN 293   // ceil(300000/1024)

// ---------------- scratch (static device globals; no allocation) ----------------
__device__ float g_w[E_EDGES];
__device__ float g_deg[N_NODES];
__device__ float g_dis[N_NODES];
__device__ int   g_cnt[N_NODES];
__device__ int   g_ptr[N_NODES + 1];
__device__ int   g_cur[N_NODES];
__device__ int   g_bsum[NB_SCAN];
__device__ int   g_boff[NB_SCAN];
__device__ int   g_adj[2 * E_EDGES];
__device__ float g_nrm[2 * E_EDGES];
__device__ __align__(16) float  g_xA[(size_t)N_NODES * DD];   // x0 (fp32)
__device__ __align__(16) __half g_h1[(size_t)N_NODES * DD];   // x1 (fp16)
__device__ __align__(16) __half g_h2[(size_t)N_NODES * DD];   // x2 (fp16)
__device__ __align__(16) float  g_acc[(size_t)N_NODES * DD];

// ---------------- init: deg = 1 (self loop), cnt = 0 ----------------
__global__ void init_kernel() {
    int i = blockIdx.x * blockDim.x + threadIdx.x;
    if (i < N_NODES) { g_deg[i] = 1.0f; g_cnt[i] = 0; }
}

// ---------------- edge MLP + degree/count accumulation ----------------
__global__ void edge_mlp_kernel(const float* __restrict__ attr,
                                const int* __restrict__ src,
                                const int* __restrict__ dst,
                                const float* __restrict__ W1,
                                const float* __restrict__ b1,
                                const float* __restrict__ W2,
                                const float* __restrict__ b2) {
    __shared__ float sW1[8 * 32];
    __shared__ float sb1[32];
    __shared__ float sW2[32];
    __shared__ float sb2;
    int t = threadIdx.x;
    if (t < 256) sW1[t] = W1[t];
    if (t < 32) { sb1[t] = b1[t]; sW2[t] = W2[t]; }
    if (t == 0) sb2 = b2[0];
    __syncthreads();

    int e = blockIdx.x * blockDim.x + t;
    if (e >= E_EDGES) return;

    const float4* ap = (const float4*)(attr + (size_t)e * 8);
    float4 a0 = ap[0], a1 = ap[1];
    float a[8] = {a0.x, a0.y, a0.z, a0.w, a1.x, a1.y, a1.z, a1.w};

    float z = sb2;
#pragma unroll
    for (int j = 0; j < 32; j++) {
        float h = sb1[j];
#pragma unroll
        for (int k = 0; k < 8; k++) h = fmaf(a[k], sW1[k * 32 + j], h);
        z = fmaf(fmaxf(h, 0.0f), sW2[j], z);
    }
    float w = 1.0f / (1.0f + __expf(-z));
    w = fmaxf(w, 1e-6f);
    g_w[e] = w;

    int s = src[e];
    int d = dst[e] + U_NODES;
    atomicAdd(&g_deg[s], w);
    atomicAdd(&g_deg[d], w);
    atomicAdd(&g_cnt[s], 1);
    atomicAdd(&g_cnt[d], 1);
}

// ---------------- phase 1: per-block sums + dis = rsqrt(deg) fused ----------------
__global__ void blocksum_kernel() {
    __shared__ int ws[32];
    int t = threadIdx.x;
    int i = blockIdx.x * 1024 + t;
    int v = 0;
    if (i < N_NODES) {
        v = g_cnt[i];
        g_dis[i] = rsqrtf(g_deg[i]);
    }
    int s0 = v;
#pragma unroll
    for (int o = 16; o; o >>= 1) s0 += __shfl_xor_sync(0xffffffffu, s0, o);
    if ((t & 31) == 0) ws[t >> 5] = s0;
    __syncthreads();
    if (t < 32) {
        int s = ws[t];
#pragma unroll
        for (int o = 16; o; o >>= 1) s += __shfl_xor_sync(0xffffffffu, s, o);
        if (t == 0) g_bsum[blockIdx.x] = s;
    }
}

// ---------------- phase 2: exclusive scan of 293 block sums (1 block) ----------------
__global__ void bscan_kernel() {
    __shared__ int ws[16];
    int t = threadIdx.x; // 512 threads
    int v = (t < NB_SCAN) ? g_bsum[t] : 0;
    int x = v;
#pragma unroll
    for (int o = 1; o < 32; o <<= 1) {
        int tmp = __shfl_up_sync(0xffffffffu, x, o);
        if ((t & 31) >= o) x += tmp;
    }
    if ((t & 31) == 31) ws[t >> 5] = x;
    __syncthreads();
    if (t < 16) {
        int s = ws[t];
#pragma unroll
        for (int o = 1; o < 16; o <<= 1) {
            int tmp = __shfl_up_sync(0x0000ffffu, s, o);
            if (t >= o) s += tmp;
        }
        ws[t] = s;
    }
    __syncthreads();
    int wp = (t >= 32) ? ws[(t >> 5) - 1] : 0;
    int incl = x + wp;
    if (t < NB_SCAN) g_boff[t] = incl - v;
    if (t == NB_SCAN - 1) g_ptr[N_NODES] = incl;
}

// ---------------- phase 3: per-block local scan + offset -> ptr, cur ----------------
__global__ void ptr_kernel() {
    __shared__ int ws[32];
    int t = threadIdx.x;
    int i = blockIdx.x * 1024 + t;
    int v = (i < N_NODES) ? g_cnt[i] : 0;
    int x = v;
#pragma unroll
    for (int o = 1; o < 32; o <<= 1) {
        int tmp = __shfl_up_sync(0xffffffffu, x, o);
        if ((t & 31) >= o) x += tmp;
    }
    if ((t & 31) == 31) ws[t >> 5] = x;
    __syncthreads();
    if (t < 32) {
        int s = ws[t];
#pragma unroll
        for (int o = 1; o < 32; o <<= 1) {
            int tmp = __shfl_up_sync(0xffffffffu, s, o);
            if (t >= o) s += tmp;
        }
        ws[t] = s;
    }
    __syncthreads();
    int wp = (t >= 32) ? ws[(t >> 5) - 1] : 0;
    int excl = (x - v) + wp + g_boff[blockIdx.x];
    if (i < N_NODES) { g_ptr[i] = excl; g_cur[i] = excl; }
}

// ---------------- scatter edges into CSR (split arrays, as in the 418us kernel) --------
__global__ void scatter_kernel(const int* __restrict__ src,
                               const int* __restrict__ dst) {
    int e = blockIdx.x * blockDim.x + threadIdx.x;
    if (e >= E_EDGES) return;
    int s = src[e];
    int d = dst[e] + U_NODES;
    float nf = g_dis[s] * g_w[e] * g_dis[d];
    int p1 = atomicAdd(&g_cur[d], 1);
    g_adj[p1] = s;
    g_nrm[p1] = nf;
    int p2 = atomicAdd(&g_cur[s], 1);
    g_adj[p2] = d;
    g_nrm[p2] = nf;
}

// ---------------- user init: l2norm(user_w) -> xA  (16 lanes/node, float4) ----------------
__global__ void user_init_kernel(const float* __restrict__ uw) {
    int gid = blockIdx.x * blockDim.x + threadIdx.x;
    int n = gid >> 4;
    if (n >= U_NODES) return;
    int lane = threadIdx.x & 15;
    float4 v = ((const float4*)uw)[(size_t)n * 16 + lane];
    float s = v.x * v.x + v.y * v.y + v.z * v.z + v.w * v.w;
#pragma unroll
    for (int o = 8; o; o >>= 1) s += __shfl_xor_sync(0xffffffffu, s, o);
    float inv = 1.0f / fmaxf(sqrtf(s), 1e-12f);
    float4 out = make_float4(v.x * inv, v.y * inv, v.z * inv, v.w * inv);
    ((float4*)g_xA)[(size_t)n * 16 + lane] = out;
}

// ---------------- item init: register-tiled GEMM (64 items/block, 4x4 tile, 256 thr) ----------------
__global__ void item_init_kernel(const float* __restrict__ audio,
                                 const float* __restrict__ artw,
                                 const float* __restrict__ albw,
                                 const int* __restrict__ aid,
                                 const int* __restrict__ alid,
                                 const float* __restrict__ Wp,
                                 const float* __restrict__ bp) {
    __shared__ __align__(16) float sIn[128 * 64];   // [k][item]  32 KB
    __shared__ float sRed[64 * 17];                 // per-item partial sums (padded)
    __shared__ float sInv[64];
    int t = threadIdx.x;
    int item0 = blockIdx.x * 64;
    int w = t >> 5, l = t & 31;
    int item_local = ((w & 1) << 5) + l;     // 0..63, lanes span items
    int item = item0 + item_local;
    bool valid = item < I_NODES;
    int cbase = w >> 1;                      // 0..3

    int a_id = valid ? aid[item] : 0;
    int al_id = valid ? alid[item] : 0;

#pragma unroll
    for (int j = 0; j < 8; j++) {
        int c = cbase + 4 * j;               // float4 chunk 0..31
        float4 v;
        if (!valid) v = make_float4(0.f, 0.f, 0.f, 0.f);
        else if (c < 16) v = ((const float4*)(audio + (size_t)item * 64))[c];
        else {
            float4 x1 = ((const float4*)(artw + (size_t)a_id * 64))[c - 16];
            float4 x2 = ((const float4*)(albw + (size_t)al_id * 64))[c - 16];
            v = make_float4(x1.x + x2.x, x1.y + x2.y, x1.z + x2.z, x1.w + x2.w);
        }
        int k = c * 4;
        sIn[(k + 0) * 64 + item_local] = v.x;
        sIn[(k + 1) * 64 + item_local] = v.y;
        sIn[(k + 2) * 64 + item_local] = v.z;
        sIn[(k + 3) * 64 + item_local] = v.w;
    }
    __syncthreads();

    int tx = t & 15;   // column group (cols tx*4..+3)
    int ty = t >> 4;   // item group   (items ty*4..+3)
    float4 bp4 = ((const float4*)bp)[tx];
    float acc[4][4];
#pragma unroll
    for (int i = 0; i < 4; i++) {
        acc[i][0] = bp4.x; acc[i][1] = bp4.y; acc[i][2] = bp4.z; acc[i][3] = bp4.w;
    }
    const float4* Wp4 = (const float4*)Wp;
#pragma unroll 4
    for (int k = 0; k < 128; k++) {
        float4 in4 = *(const float4*)(sIn + k * 64 + ty * 4);
        float4 w4 = __ldg(Wp4 + k * 16 + tx);   // L1-resident (32 KB)
        float vi[4] = {in4.x, in4.y, in4.z, in4.w};
#pragma unroll
        for (int i = 0; i < 4; i++) {
            acc[i][0] = fmaf(vi[i], w4.x, acc[i][0]);
            acc[i][1] = fmaf(vi[i], w4.y, acc[i][1]);
            acc[i][2] = fmaf(vi[i], w4.z, acc[i][2]);
            acc[i][3] = fmaf(vi[i], w4.w, acc[i][3]);
        }
    }
#pragma unroll
    for (int i = 0; i < 4; i++) {
        float p = acc[i][0] * acc[i][0] + acc[i][1] * acc[i][1]
                + acc[i][2] * acc[i][2] + acc[i][3] * acc[i][3];
        sRed[(ty * 4 + i) * 17 + tx] = p;
    }
    __syncthreads();
    if (t < 64) {
        float s = 0.f;
#pragma unroll
        for (int q = 0; q < 16; q++) s += sRed[t * 17 + q];
        sInv[t] = 1.0f / fmaxf(sqrtf(s), 1e-12f);
    }
    __syncthreads();
#pragma unroll
    for (int i = 0; i < 4; i++) {
        int il = ty * 4 + i;
        int it = item0 + il;
        if (it < I_NODES) {
            float inv = sInv[il];
            float4 o = make_float4(acc[i][0] * inv, acc[i][1] * inv,
                                   acc[i][2] * inv, acc[i][3] * inv);
            ((float4*)g_xA)[(size_t)(U_NODES + it) * 16 + tx] = o;
        }
    }
}

// ---------------- fp16 pack/unpack helpers (4 halves <-> uint2) ----------------
__device__ __forceinline__ uint2 pack4h(float4 f) {
    __half2 p0 = __floats2half2_rn(f.x, f.y);
    __half2 p1 = __floats2half2_rn(f.z, f.w);
    uint2 r;
    r.x = *reinterpret_cast<unsigned*>(&p0);
    r.y = *reinterpret_cast<unsigned*>(&p1);
    return r;
}
__device__ __forceinline__ float4 unpack4h(uint2 q) {
    __half2 p0 = *reinterpret_cast<__half2*>(&q.x);
    __half2 p1 = *reinterpret_cast<__half2*>(&q.y);
    float2 f0 = __half22float2(p0);
    float2 f1 = __half22float2(p1);
    return make_float4(f0.x, f0.y, f1.x, f1.y);
}

// ---------------- one LGConv layer (16 lanes/node) ----------------
// MODE 0: layer1  xA(f32) -> h1(f16); acc = x0 + x1 (fp32, no acc read)
// MODE 1: layer2  h1(f16) -> h2(f16); acc += x2
// MODE 2: layer3  h2(f16) -> out = l2norm((acc + x3)/4)
template<int MODE>
__global__ void gather_kernel(float* __restrict__ outp) {
    int gid = blockIdx.x * blockDim.x + threadIdx.x;
    int n = gid >> 4;
    if (n >= N_NODES) return;
    int lane = threadIdx.x & 15;

    float dv = g_dis[n];
    float sw = dv * dv;
    float4 a, a2 = make_float4(0.f, 0.f, 0.f, 0.f);
    float4 self;

    if (MODE == 0) {
        self = __ldg((const float4*)g_xA + (size_t)n * 16 + lane);
    } else {
        const uint2* hx = (MODE == 1) ? (const uint2*)g_h1 : (const uint2*)g_h2;
        self = unpack4h(__ldg(hx + (size_t)n * 16 + lane));
    }
    a = make_float4(self.x * sw, self.y * sw, self.z * sw, self.w * sw);

    int e = g_ptr[n];
    int end = g_ptr[n + 1];

    if (MODE == 0) {
        const float4* xr = (const float4*)g_xA;
        for (; e + 4 <= end; e += 4) {
            int j0 = __ldg(g_adj + e + 0);
            int j1 = __ldg(g_adj + e + 1);
            int j2 = __ldg(g_adj + e + 2);
            int j3 = __ldg(g_adj + e + 3);
            float v0 = __ldg(g_nrm + e + 0);
            float v1 = __ldg(g_nrm + e + 1);
            float v2 = __ldg(g_nrm + e + 2);
            float v3 = __ldg(g_nrm + e + 3);
            float4 x0 = __ldg(xr + (size_t)j0 * 16 + lane);
            float4 x1 = __ldg(xr + (size_t)j1 * 16 + lane);
            float4 x2 = __ldg(xr + (size_t)j2 * 16 + lane);
            float4 x3 = __ldg(xr + (size_t)j3 * 16 + lane);
            a.x  = fmaf(v0, x0.x, a.x);  a.y  = fmaf(v0, x0.y, a.y);
            a.z  = fmaf(v0, x0.z, a.z);  a.w  = fmaf(v0, x0.w, a.w);
            a.x  = fmaf(v1, x1.x, a.x);  a.y  = fmaf(v1, x1.y, a.y);
            a.z  = fmaf(v1, x1.z, a.z);  a.w  = fmaf(v1, x1.w, a.w);
            a2.x = fmaf(v2, x2.x, a2.x); a2.y = fmaf(v2, x2.y, a2.y);
            a2.z = fmaf(v2, x2.z, a2.z); a2.w = fmaf(v2, x2.w, a2.w);
            a2.x = fmaf(v3, x3.x, a2.x); a2.y = fmaf(v3, x3.y, a2.y);
            a2.z = fmaf(v3, x3.z, a2.z); a2.w = fmaf(v3, x3.w, a2.w);
        }
        for (; e < end; e++) {
            int j0 = __ldg(g_adj + e);
            float v0 = __ldg(g_nrm + e);
            float4 x0 = __ldg(xr + (size_t)j0 * 16 + lane);
            a.x = fmaf(v0, x0.x, a.x); a.y = fmaf(v0, x0.y, a.y);
            a.z = fmaf(v0, x0.z, a.z); a.w = fmaf(v0, x0.w, a.w);
        }
    } else {
        const uint2* hx = (MODE == 1) ? (const uint2*)g_h1 : (const uint2*)g_h2;
        for (; e + 4 <= end; e += 4) {
            int j0 = __ldg(g_adj + e + 0);
            int j1 = __ldg(g_adj + e + 1);
            int j2 = __ldg(g_adj + e + 2);
            int j3 = __ldg(g_adj + e + 3);
            float v0 = __ldg(g_nrm + e + 0);
            float v1 = __ldg(g_nrm + e + 1);
            float v2 = __ldg(g_nrm + e + 2);
            float v3 = __ldg(g_nrm + e + 3);
            float4 x0 = unpack4h(__ldg(hx + (size_t)j0 * 16 + lane));
            float4 x1 = unpack4h(__ldg(hx + (size_t)j1 * 16 + lane));
            float4 x2 = unpack4h(__ldg(hx + (size_t)j2 * 16 + lane));
            float4 x3 = unpack4h(__ldg(hx + (size_t)j3 * 16 + lane));
            a.x  = fmaf(v0, x0.x, a.x);  a.y  = fmaf(v0, x0.y, a.y);
            a.z  = fmaf(v0, x0.z, a.z);  a.w  = fmaf(v0, x0.w, a.w);
            a.x  = fmaf(v1, x1.x, a.x);  a.y  = fmaf(v1, x1.y, a.y);
            a.z  = fmaf(v1, x1.z, a.z);  a.w  = fmaf(v1, x1.w, a.w);
            a2.x = fmaf(v2, x2.x, a2.x); a2.y = fmaf(v2, x2.y, a2.y);
            a2.z = fmaf(v2, x2.z, a2.z); a2.w = fmaf(v2, x2.w, a2.w);
            a2.x = fmaf(v3, x3.x, a2.x); a2.y = fmaf(v3, x3.y, a2.y);
            a2.z = fmaf(v3, x3.z, a2.z); a2.w = fmaf(v3, x3.w, a2.w);
        }
        for (; e < end; e++) {
            int j0 = __ldg(g_adj + e);
            float v0 = __ldg(g_nrm + e);
            float4 x0 = unpack4h(__ldg(hx + (size_t)j0 * 16 + lane));
            a.x = fmaf(v0, x0.x, a.x); a.y = fmaf(v0, x0.y, a.y);
            a.z = fmaf(v0, x0.z, a.z); a.w = fmaf(v0, x0.w, a.w);
        }
    }
    a.x += a2.x; a.y += a2.y; a.z += a2.z; a.w += a2.w;

    if (MODE == 0) {
        ((uint2*)g_h1)[(size_t)n * 16 + lane] = pack4h(a);
        float4 c = make_float4(self.x + a.x, self.y + a.y, self.z + a.z, self.w + a.w);
        ((float4*)g_acc)[(size_t)n * 16 + lane] = c;
    } else if (MODE == 1) {
        ((uint2*)g_h2)[(size_t)n * 16 + lane] = pack4h(a);
        float4 c = ((const float4*)g_acc)[(size_t)n * 16 + lane];
        c.x += a.x; c.y += a.y; c.z += a.z; c.w += a.w;
        ((float4*)g_acc)[(size_t)n * 16 + lane] = c;
    } else {
        float4 c = ((const float4*)g_acc)[(size_t)n * 16 + lane];
        c.x = (c.x + a.x) * 0.25f;
        c.y = (c.y + a.y) * 0.25f;
        c.z = (c.z + a.z) * 0.25f;
        c.w = (c.w + a.w) * 0.25f;
        float s = c.x * c.x + c.y * c.y + c.z * c.z + c.w * c.w;
#pragma unroll
        for (int o = 8; o; o >>= 1) s += __shfl_xor_sync(0xffffffffu, s, o);
        float inv = 1.0f / fmaxf(sqrtf(s), 1e-12f);
        ((float4*)outp)[(size_t)n * 16 + lane] =
            make_float4(c.x * inv, c.y * inv, c.z * inv, c.w * inv);
    }
}

// ---------------- side stream + events, created once at static-init time ----------------
__global__ void warmup_kernel() {}

namespace {
struct SideStream {
    cudaStream_t s2 = 0;
    cudaEvent_t evFork = 0, evJoin = 0;
    bool ok = false;
    SideStream() {
        if (cudaStreamCreateWithFlags(&s2, cudaStreamNonBlocking) != cudaSuccess) return;
        if (cudaEventCreateWithFlags(&evFork, cudaEventDisableTiming) != cudaSuccess) return;
        if (cudaEventCreateWithFlags(&evJoin, cudaEventDisableTiming) != cudaSuccess) return;
        warmup_kernel<<<1, 32>>>();
        warmup_kernel<<<1, 32, 0, s2>>>();
        if (cudaDeviceSynchronize() != cudaSuccess) return;
        ok = true;
    }
};
SideStream g_side;
}

extern "C" void kernel_launch(void* const* d_in, const int* in_sizes, int n_in,
                              void* d_out, int out_size) {
    const int*   edge_src   = (const int*)d_in[0];
    const int*   edge_dst   = (const int*)d_in[1];
    const float* edge_attr  = (const float*)d_in[2];
    const float* user_w     = (const float*)d_in[3];
    const float* artist_w   = (const float*)d_in[4];
    const float* album_w    = (const float*)d_in[5];
    const float* item_audio = (const float*)d_in[6];
    const int*   artist_ids = (const int*)d_in[7];
    const int*   album_ids  = (const int*)d_in[8];
    const float* Wp         = (const float*)d_in[9];
    const float* bp         = (const float*)d_in[10];
    const float* W1         = (const float*)d_in[11];
    const float* b1         = (const float*)d_in[12];
    const float* W2         = (const float*)d_in[13];
    const float* b2         = (const float*)d_in[14];
    float* out = (float*)d_out;

    const int TPB = 256;
    bool fork = g_side.ok;
    cudaStream_t sB = fork ? g_side.s2 : (cudaStream_t)0;

    if (fork) {
        cudaEventRecord(g_side.evFork, 0);
        cudaStreamWaitEvent(sB, g_side.evFork, 0);
    }

    // ---- chain B (side stream): node feature init ----
    user_init_kernel<<<(U_NODES * 16 + TPB - 1) / TPB, TPB, 0, sB>>>(user_w);
    item_init_kernel<<<(I_NODES + 63) / 64, TPB, 0, sB>>>(item_audio, artist_w, album_w,
                                                          artist_ids, album_ids, Wp, bp);
    if (fork) cudaEventRecord(g_side.evJoin, sB);

    // ---- chain A (main stream): graph build ----
    init_kernel<<<(N_NODES + TPB - 1) / TPB, TPB>>>();
    edge_mlp_kernel<<<(E_EDGES + TPB - 1) / TPB, TPB>>>(edge_attr, edge_src, edge_dst,
                                                        W1, b1, W2, b2);
    blocksum_kernel<<<NB_SCAN, 1024>>>();   // also computes g_dis
    bscan_kernel<<<1, 512>>>();
    ptr_kernel<<<NB_SCAN, 1024>>>();
    scatter_kernel<<<(E_EDGES + TPB - 1) / TPB, TPB>>>(edge_src, edge_dst);

    if (fork) cudaStreamWaitEvent((cudaStream_t)0, g_side.evJoin, 0);

    // ---- 3 propagation layers ----
    int nblocks = (N_NODES * 16 + TPB - 1) / TPB;
    gather_kernel<0><<<nblocks, TPB>>>(nullptr);
    gather_kernel<1><<<nblocks, TPB>>>(nullptr);
    gather_kernel<2><<<nblocks, TPB>>>(out);
}

// round 8
// speedup vs baseline: 1.3609x; 1.1554x over previous
#include <cuda_runtime.h>
#include <cuda_fp16.h>
#include <math.h>

#define U_NODES 200000
#define I_NODES 100000
#define N_NODES 300000
#define E_EDGES 1000000
#define DD 64
#define NB_SCAN 293   // ceil(300000/1024)

// ---------------- scratch (static device globals; no allocation) ----------------
__device__ float g_w[E_EDGES];
__device__ float g_deg[N_NODES];
__device__ float g_dis[N_NODES];
__device__ int   g_cnt[N_NODES];
__device__ int   g_ptr[N_NODES + 1];
__device__ int   g_cur[N_NODES];
__device__ int   g_bsum[NB_SCAN];
__device__ int   g_boff[NB_SCAN];
__device__ int   g_adj[2 * E_EDGES];
__device__ float g_nrm[2 * E_EDGES];
__device__ __align__(16) __half g_h0[(size_t)N_NODES * DD];   // x0 (fp16)
__device__ __align__(16) __half g_h1[(size_t)N_NODES * DD];   // x1 (fp16)
__device__ __align__(16) __half g_h2[(size_t)N_NODES * DD];   // x2 (fp16)

// ---------------- fp16 pack/unpack helpers (4 halves <-> uint2) ----------------
__device__ __forceinline__ uint2 pack4h(float4 f) {
    __half2 p0 = __floats2half2_rn(f.x, f.y);
    __half2 p1 = __floats2half2_rn(f.z, f.w);
    uint2 r;
    r.x = *reinterpret_cast<unsigned*>(&p0);
    r.y = *reinterpret_cast<unsigned*>(&p1);
    return r;
}
__device__ __forceinline__ float4 unpack4h(uint2 q) {
    __half2 p0 = *reinterpret_cast<__half2*>(&q.x);
    __half2 p1 = *reinterpret_cast<__half2*>(&q.y);
    float2 f0 = __half22float2(p0);
    float2 f1 = __half22float2(p1);
    return make_float4(f0.x, f0.y, f1.x, f1.y);
}

// ---------------- init: deg = 1 (self loop), cnt = 0 ----------------
__global__ void init_kernel() {
    int i = blockIdx.x * blockDim.x + threadIdx.x;
    if (i < N_NODES) { g_deg[i] = 1.0f; g_cnt[i] = 0; }
}

// ---------------- edge MLP + degree/count accumulation ----------------
__global__ void edge_mlp_kernel(const float* __restrict__ attr,
                                const int* __restrict__ src,
                                const int* __restrict__ dst,
                                const float* __restrict__ W1,
                                const float* __restrict__ b1,
                                const float* __restrict__ W2,
                                const float* __restrict__ b2) {
    __shared__ float sW1[8 * 32];
    __shared__ float sb1[32];
    __shared__ float sW2[32];
    __shared__ float sb2;
    int t = threadIdx.x;
    if (t < 256) sW1[t] = W1[t];
    if (t < 32) { sb1[t] = b1[t]; sW2[t] = W2[t]; }
    if (t == 0) sb2 = b2[0];
    __syncthreads();

    int e = blockIdx.x * blockDim.x + t;
    if (e >= E_EDGES) return;

    const float4* ap = (const float4*)(attr + (size_t)e * 8);
    float4 a0 = ap[0], a1 = ap[1];
    float a[8] = {a0.x, a0.y, a0.z, a0.w, a1.x, a1.y, a1.z, a1.w};

    float z = sb2;
#pragma unroll
    for (int j = 0; j < 32; j++) {
        float h = sb1[j];
#pragma unroll
        for (int k = 0; k < 8; k++) h = fmaf(a[k], sW1[k * 32 + j], h);
        z = fmaf(fmaxf(h, 0.0f), sW2[j], z);
    }
    float w = 1.0f / (1.0f + __expf(-z));
    w = fmaxf(w, 1e-6f);
    g_w[e] = w;

    int s = src[e];
    int d = dst[e] + U_NODES;
    atomicAdd(&g_deg[s], w);
    atomicAdd(&g_deg[d], w);
    atomicAdd(&g_cnt[s], 1);
    atomicAdd(&g_cnt[d], 1);
}

// ---------------- phase 1: per-block sums + dis = rsqrt(deg) fused ----------------
__global__ void blocksum_kernel() {
    __shared__ int ws[32];
    int t = threadIdx.x;
    int i = blockIdx.x * 1024 + t;
    int v = 0;
    if (i < N_NODES) {
        v = g_cnt[i];
        g_dis[i] = rsqrtf(g_deg[i]);
    }
    int s0 = v;
#pragma unroll
    for (int o = 16; o; o >>= 1) s0 += __shfl_xor_sync(0xffffffffu, s0, o);
    if ((t & 31) == 0) ws[t >> 5] = s0;
    __syncthreads();
    if (t < 32) {
        int s = ws[t];
#pragma unroll
        for (int o = 16; o; o >>= 1) s += __shfl_xor_sync(0xffffffffu, s, o);
        if (t == 0) g_bsum[blockIdx.x] = s;
    }
}

// ---------------- phase 2: exclusive scan of 293 block sums (1 block) ----------------
__global__ void bscan_kernel() {
    __shared__ int ws[16];
    int t = threadIdx.x; // 512 threads
    int v = (t < NB_SCAN) ? g_bsum[t] : 0;
    int x = v;
#pragma unroll
    for (int o = 1; o < 32; o <<= 1) {
        int tmp = __shfl_up_sync(0xffffffffu, x, o);
        if ((t & 31) >= o) x += tmp;
    }
    if ((t & 31) == 31) ws[t >> 5] = x;
    __syncthreads();
    if (t < 16) {
        int s = ws[t];
#pragma unroll
        for (int o = 1; o < 16; o <<= 1) {
            int tmp = __shfl_up_sync(0x0000ffffu, s, o);
            if (t >= o) s += tmp;
        }
        ws[t] = s;
    }
    __syncthreads();
    int wp = (t >= 32) ? ws[(t >> 5) - 1] : 0;
    int incl = x + wp;
    if (t < NB_SCAN) g_boff[t] = incl - v;
    if (t == NB_SCAN - 1) g_ptr[N_NODES] = incl;
}

// ---------------- phase 3: per-block local scan + offset -> ptr, cur ----------------
__global__ void ptr_kernel() {
    __shared__ int ws[32];
    int t = threadIdx.x;
    int i = blockIdx.x * 1024 + t;
    int v = (i < N_NODES) ? g_cnt[i] : 0;
    int x = v;
#pragma unroll
    for (int o = 1; o < 32; o <<= 1) {
        int tmp = __shfl_up_sync(0xffffffffu, x, o);
        if ((t & 31) >= o) x += tmp;
    }
    if ((t & 31) == 31) ws[t >> 5] = x;
    __syncthreads();
    if (t < 32) {
        int s = ws[t];
#pragma unroll
        for (int o = 1; o < 32; o <<= 1) {
            int tmp = __shfl_up_sync(0xffffffffu, s, o);
            if (t >= o) s += tmp;
        }
        ws[t] = s;
    }
    __syncthreads();
    int wp = (t >= 32) ? ws[(t >> 5) - 1] : 0;
    int excl = (x - v) + wp + g_boff[blockIdx.x];
    if (i < N_NODES) { g_ptr[i] = excl; g_cur[i] = excl; }
}

// ---------------- scatter edges into CSR (split arrays) ----------------
__global__ void scatter_kernel(const int* __restrict__ src,
                               const int* __restrict__ dst) {
    int e = blockIdx.x * blockDim.x + threadIdx.x;
    if (e >= E_EDGES) return;
    int s = src[e];
    int d = dst[e] + U_NODES;
    float nf = g_dis[s] * g_w[e] * g_dis[d];
    int p1 = atomicAdd(&g_cur[d], 1);
    g_adj[p1] = s;
    g_nrm[p1] = nf;
    int p2 = atomicAdd(&g_cur[s], 1);
    g_adj[p2] = d;
    g_nrm[p2] = nf;
}

// ---------------- user init: l2norm(user_w) -> h0 (fp16) ----------------
__global__ void user_init_kernel(const float* __restrict__ uw) {
    int gid = blockIdx.x * blockDim.x + threadIdx.x;
    int n = gid >> 4;
    if (n >= U_NODES) return;
    int lane = threadIdx.x & 15;
    float4 v = ((const float4*)uw)[(size_t)n * 16 + lane];
    float s = v.x * v.x + v.y * v.y + v.z * v.z + v.w * v.w;
#pragma unroll
    for (int o = 8; o; o >>= 1) s += __shfl_xor_sync(0xffffffffu, s, o);
    float inv = 1.0f / fmaxf(sqrtf(s), 1e-12f);
    float4 out = make_float4(v.x * inv, v.y * inv, v.z * inv, v.w * inv);
    ((uint2*)g_h0)[(size_t)n * 16 + lane] = pack4h(out);
}

// ---------------- item init: register-tiled GEMM -> h0 (fp16) ----------------
__global__ void item_init_kernel(const float* __restrict__ audio,
                                 const float* __restrict__ artw,
                                 const float* __restrict__ albw,
                                 const int* __restrict__ aid,
                                 const int* __restrict__ alid,
                                 const float* __restrict__ Wp,
                                 const float* __restrict__ bp) {
    __shared__ __align__(16) float sIn[128 * 64];   // [k][item]  32 KB
    __shared__ float sRed[64 * 17];                 // per-item partial sums (padded)
    __shared__ float sInv[64];
    int t = threadIdx.x;
    int item0 = blockIdx.x * 64;
    int w = t >> 5, l = t & 31;
    int item_local = ((w & 1) << 5) + l;     // 0..63, lanes span items
    int item = item0 + item_local;
    bool valid = item < I_NODES;
    int cbase = w >> 1;                      // 0..3

    int a_id = valid ? aid[item] : 0;
    int al_id = valid ? alid[item] : 0;

#pragma unroll
    for (int j = 0; j < 8; j++) {
        int c = cbase + 4 * j;               // float4 chunk 0..31
        float4 v;
        if (!valid) v = make_float4(0.f, 0.f, 0.f, 0.f);
        else if (c < 16) v = ((const float4*)(audio + (size_t)item * 64))[c];
        else {
            float4 x1 = ((const float4*)(artw + (size_t)a_id * 64))[c - 16];
            float4 x2 = ((const float4*)(albw + (size_t)al_id * 64))[c - 16];
            v = make_float4(x1.x + x2.x, x1.y + x2.y, x1.z + x2.z, x1.w + x2.w);
        }
        int k = c * 4;
        sIn[(k + 0) * 64 + item_local] = v.x;
        sIn[(k + 1) * 64 + item_local] = v.y;
        sIn[(k + 2) * 64 + item_local] = v.z;
        sIn[(k + 3) * 64 + item_local] = v.w;
    }
    __syncthreads();

    int tx = t & 15;   // column group (cols tx*4..+3)
    int ty = t >> 4;   // item group   (items ty*4..+3)
    float4 bp4 = ((const float4*)bp)[tx];
    float acc[4][4];
#pragma unroll
    for (int i = 0; i < 4; i++) {
        acc[i][0] = bp4.x; acc[i][1] = bp4.y; acc[i][2] = bp4.z; acc[i][3] = bp4.w;
    }
    const float4* Wp4 = (const float4*)Wp;
#pragma unroll 4
    for (int k = 0; k < 128; k++) {
        float4 in4 = *(const float4*)(sIn + k * 64 + ty * 4);
        float4 w4 = __ldg(Wp4 + k * 16 + tx);   // L1-resident (32 KB)
        float vi[4] = {in4.x, in4.y, in4.z, in4.w};
#pragma unroll
        for (int i = 0; i < 4; i++) {
            acc[i][0] = fmaf(vi[i], w4.x, acc[i][0]);
            acc[i][1] = fmaf(vi[i], w4.y, acc[i][1]);
            acc[i][2] = fmaf(vi[i], w4.z, acc[i][2]);
            acc[i][3] = fmaf(vi[i], w4.w, acc[i][3]);
        }
    }
#pragma unroll
    for (int i = 0; i < 4; i++) {
        float p = acc[i][0] * acc[i][0] + acc[i][1] * acc[i][1]
                + acc[i][2] * acc[i][2] + acc[i][3] * acc[i][3];
        sRed[(ty * 4 + i) * 17 + tx] = p;
    }
    __syncthreads();
    if (t < 64) {
        float s = 0.f;
#pragma unroll
        for (int q = 0; q < 16; q++) s += sRed[t * 17 + q];
        sInv[t] = 1.0f / fmaxf(sqrtf(s), 1e-12f);
    }
    __syncthreads();
#pragma unroll
    for (int i = 0; i < 4; i++) {
        int il = ty * 4 + i;
        int it = item0 + il;
        if (it < I_NODES) {
            float inv = sInv[il];
            float4 o = make_float4(acc[i][0] * inv, acc[i][1] * inv,
                                   acc[i][2] * inv, acc[i][3] * inv);
            ((uint2*)g_h0)[(size_t)(U_NODES + it) * 16 + tx] = pack4h(o);
        }
    }
}

// ---------------- one LGConv layer (16 lanes/node, all-fp16 rows) ----------------
// MODE 0: h0 -> h1
// MODE 1: h1 -> h2
// MODE 2: h2 -> out = l2norm((x0 + x1 + x2 + x3)/4)  (x3 computed here; no acc array)
template<int MODE>
__global__ void gather_kernel(float* __restrict__ outp) {
    const uint2* hin = (MODE == 0) ? (const uint2*)g_h0
                     : (MODE == 1) ? (const uint2*)g_h1
                                   : (const uint2*)g_h2;

    int gid = blockIdx.x * blockDim.x + threadIdx.x;
    int n = gid >> 4;
    if (n >= N_NODES) return;
    int lane = threadIdx.x & 15;

    float dv = g_dis[n];
    float sw = dv * dv;
    float4 self = unpack4h(__ldg(hin + (size_t)n * 16 + lane));
    float4 a = make_float4(self.x * sw, self.y * sw, self.z * sw, self.w * sw);
    float4 a2 = make_float4(0.f, 0.f, 0.f, 0.f);

    int e = g_ptr[n];
    int end = g_ptr[n + 1];
    for (; e + 4 <= end; e += 4) {
        int j0 = __ldg(g_adj + e + 0);
        int j1 = __ldg(g_adj + e + 1);
        int j2 = __ldg(g_adj + e + 2);
        int j3 = __ldg(g_adj + e + 3);
        float v0 = __ldg(g_nrm + e + 0);
        float v1 = __ldg(g_nrm + e + 1);
        float v2 = __ldg(g_nrm + e + 2);
        float v3 = __ldg(g_nrm + e + 3);
        float4 x0 = unpack4h(__ldg(hin + (size_t)j0 * 16 + lane));
        float4 x1 = unpack4h(__ldg(hin + (size_t)j1 * 16 + lane));
        float4 x2 = unpack4h(__ldg(hin + (size_t)j2 * 16 + lane));
        float4 x3 = unpack4h(__ldg(hin + (size_t)j3 * 16 + lane));
        a.x  = fmaf(v0, x0.x, a.x);  a.y  = fmaf(v0, x0.y, a.y);
        a.z  = fmaf(v0, x0.z, a.z);  a.w  = fmaf(v0, x0.w, a.w);
        a.x  = fmaf(v1, x1.x, a.x);  a.y  = fmaf(v1, x1.y, a.y);
        a.z  = fmaf(v1, x1.z, a.z);  a.w  = fmaf(v1, x1.w, a.w);
        a2.x = fmaf(v2, x2.x, a2.x); a2.y = fmaf(v2, x2.y, a2.y);
        a2.z = fmaf(v2, x2.z, a2.z); a2.w = fmaf(v2, x2.w, a2.w);
        a2.x = fmaf(v3, x3.x, a2.x); a2.y = fmaf(v3, x3.y, a2.y);
        a2.z = fmaf(v3, x3.z, a2.z); a2.w = fmaf(v3, x3.w, a2.w);
    }
    for (; e < end; e++) {
        int j0 = __ldg(g_adj + e);
        float v0 = __ldg(g_nrm + e);
        float4 x0 = unpack4h(__ldg(hin + (size_t)j0 * 16 + lane));
        a.x = fmaf(v0, x0.x, a.x); a.y = fmaf(v0, x0.y, a.y);
        a.z = fmaf(v0, x0.z, a.z); a.w = fmaf(v0, x0.w, a.w);
    }
    a.x += a2.x; a.y += a2.y; a.z += a2.z; a.w += a2.w;

    if (MODE == 0) {
        ((uint2*)g_h1)[(size_t)n * 16 + lane] = pack4h(a);
    } else if (MODE == 1) {
        ((uint2*)g_h2)[(size_t)n * 16 + lane] = pack4h(a);
    } else {
        // layer-sum readout: x0 + x1 + x2(self) + x3(a), all fp32 accumulation
        float4 x0 = unpack4h(__ldg((const uint2*)g_h0 + (size_t)n * 16 + lane));
        float4 x1 = unpack4h(__ldg((const uint2*)g_h1 + (size_t)n * 16 + lane));
        float4 c;
        c.x = (x0.x + x1.x + self.x + a.x) * 0.25f;
        c.y = (x0.y + x1.y + self.y + a.y) * 0.25f;
        c.z = (x0.z + x1.z + self.z + a.z) * 0.25f;
        c.w = (x0.w + x1.w + self.w + a.w) * 0.25f;
        float s = c.x * c.x + c.y * c.y + c.z * c.z + c.w * c.w;
#pragma unroll
        for (int o = 8; o; o >>= 1) s += __shfl_xor_sync(0xffffffffu, s, o);
        float inv = 1.0f / fmaxf(sqrtf(s), 1e-12f);
        ((float4*)outp)[(size_t)n * 16 + lane] =
            make_float4(c.x * inv, c.y * inv, c.z * inv, c.w * inv);
    }
}

// ---------------- side stream + events, created once at static-init time ----------------
__global__ void warmup_kernel() {}

namespace {
struct SideStream {
    cudaStream_t s2 = 0;
    cudaEvent_t evFork = 0, evJoin = 0;
    bool ok = false;
    SideStream() {
        if (cudaStreamCreateWithFlags(&s2, cudaStreamNonBlocking) != cudaSuccess) return;
        if (cudaEventCreateWithFlags(&evFork, cudaEventDisableTiming) != cudaSuccess) return;
        if (cudaEventCreateWithFlags(&evJoin, cudaEventDisableTiming) != cudaSuccess) return;
        warmup_kernel<<<1, 32>>>();
        warmup_kernel<<<1, 32, 0, s2>>>();
        if (cudaDeviceSynchronize() != cudaSuccess) return;
        ok = true;
    }
};
SideStream g_side;
}

extern "C" void kernel_launch(void* const* d_in, const int* in_sizes, int n_in,
                              void* d_out, int out_size) {
    const int*   edge_src   = (const int*)d_in[0];
    const int*   edge_dst   = (const int*)d_in[1];
    const float* edge_attr  = (const float*)d_in[2];
    const float* user_w     = (const float*)d_in[3];
    const float* artist_w   = (const float*)d_in[4];
    const float* album_w    = (const float*)d_in[5];
    const float* item_audio = (const float*)d_in[6];
    const int*   artist_ids = (const int*)d_in[7];
    const int*   album_ids  = (const int*)d_in[8];
    const float* Wp         = (const float*)d_in[9];
    const float* bp         = (const float*)d_in[10];
    const float* W1         = (const float*)d_in[11];
    const float* b1         = (const float*)d_in[12];
    const float* W2         = (const float*)d_in[13];
    const float* b2         = (const float*)d_in[14];
    float* out = (float*)d_out;

    const int TPB = 256;
    bool fork = g_side.ok;
    cudaStream_t sB = fork ? g_side.s2 : (cudaStream_t)0;

    if (fork) {
        cudaEventRecord(g_side.evFork, 0);
        cudaStreamWaitEvent(sB, g_side.evFork, 0);
    }

    // ---- chain B (side stream): node feature init ----
    user_init_kernel<<<(U_NODES * 16 + TPB - 1) / TPB, TPB, 0, sB>>>(user_w);
    item_init_kernel<<<(I_NODES + 63) / 64, TPB, 0, sB>>>(item_audio, artist_w, album_w,
                                                          artist_ids, album_ids, Wp, bp);
    if (fork) cudaEventRecord(g_side.evJoin, sB);

    // ---- chain A (main stream): graph build ----
    init_kernel<<<(N_NODES + TPB - 1) / TPB, TPB>>>();
    edge_mlp_kernel<<<(E_EDGES + TPB - 1) / TPB, TPB>>>(edge_attr, edge_src, edge_dst,
                                                        W1, b1, W2, b2);
    blocksum_kernel<<<NB_SCAN, 1024>>>();   // also computes g_dis
    bscan_kernel<<<1, 512>>>();
    ptr_kernel<<<NB_SCAN, 1024>>>();
    scatter_kernel<<<(E_EDGES + TPB - 1) / TPB, TPB>>>(edge_src, edge_dst);

    if (fork) cudaStreamWaitEvent((cudaStream_t)0, g_side.evJoin, 0);

    // ---- 3 propagation layers ----
    int nblocks = (N_NODES * 16 + TPB - 1) / TPB;
    gather_kernel<0><<<nblocks, TPB>>>(nullptr);
    gather_kernel<1><<<nblocks, TPB>>>(nullptr);
    gather_kernel<2><<<nblocks, TPB>>>(out);
}